// round 5
// baseline (speedup 1.0000x reference)
#include <cuda_runtime.h>
#include <cstdint>

// Problem constants (fixed by the dataset)
#define BVAL   2048
#define TVAL   2048
#define HVAL   64
#define NB     4                    // batches per thread/group
#define GROUPS 4                    // barrier groups per CTA
#define BTILE  (NB * GROUPS)        // 16 batches per CTA
#define THREADS (GROUPS * HVAL)     // 256 threads
#define GRID   (BVAL / BTILE)       // 128 CTAs -> single wave

// ---------- packed f32x2 helpers (Blackwell) ----------
__device__ __forceinline__ unsigned long long ffma2(unsigned long long a,
                                                    unsigned long long b,
                                                    unsigned long long c) {
    unsigned long long d;
    asm("fma.rn.f32x2 %0, %1, %2, %3;" : "=l"(d) : "l"(a), "l"(b), "l"(c));
    return d;
}
__device__ __forceinline__ unsigned long long fadd2(unsigned long long a,
                                                    unsigned long long b) {
    unsigned long long d;
    asm("add.rn.f32x2 %0, %1, %2;" : "=l"(d) : "l"(a), "l"(b));
    return d;
}
__device__ __forceinline__ float lo32(unsigned long long v) {
    return __uint_as_float((unsigned)v);
}
__device__ __forceinline__ float hi32(unsigned long long v) {
    return __uint_as_float((unsigned)(v >> 32));
}
__device__ __forceinline__ unsigned long long pack2(float lo, float hi) {
    return (unsigned long long)__float_as_uint(lo) |
           ((unsigned long long)__float_as_uint(hi) << 32);
}

// tanh via ex2/rcp approx: rel err ~1e-7 per step (safe over 2048 recurrent steps).
__device__ __forceinline__ float fast_tanh(float s) {
    float z = fminf(s * 2.885390082f, 126.0f);   // 2*log2(e)*s, clamped
    float p; asm("ex2.approx.f32 %0, %1;" : "=f"(p) : "f"(z));
    float num = p - 1.0f;
    float den = p + 1.0f;
    float r; asm("rcp.approx.f32 %0, %1;" : "=f"(r) : "f"(den));
    return num * r;   // z << 0 -> p = 0 -> exactly -1
}

// Named barrier over one group's 64 threads (2 warps, NB batches). ids 1..GROUPS.
__device__ __forceinline__ void barrier_group(int g) {
    asm volatile("bar.sync %0, 64;" :: "r"(g + 1) : "memory");
}

__global__ void __launch_bounds__(THREADS, 1)
rnn_kernel(const float* __restrict__ x,     // [B,T,2]
           const float* __restrict__ W_ih,  // [64,2]
           const float* __restrict__ W_hh,  // [64,64]
           const float* __restrict__ b_ih,  // [64]
           const float* __restrict__ b_hh,  // [64]
           const float* __restrict__ W_fc,  // [2,64]
           const float* __restrict__ b_fc,  // [2]
           float* __restrict__ out)         // [B,2]
{
    // double-buffered hidden state, batch-major (contiguous 64 floats per batch)
    __shared__ __align__(16) float hbuf[2][BTILE][HVAL];

    const int tid = threadIdx.x;
    const int j   = tid & (HVAL - 1);   // output index this thread owns
    const int g   = tid >> 6;           // group 0..GROUPS-1
    const int bl0 = NB * g;             // first local batch of this group
    const int b0  = blockIdx.x * BTILE + bl0;

    // W_hh row j, k-packed into 32 x u64 registers
    unsigned long long w2[HVAL / 2];
    {
        const unsigned long long* wrow =
            reinterpret_cast<const unsigned long long*>(W_hh + j * HVAL);
        #pragma unroll
        for (int k = 0; k < HVAL / 2; k++) w2[k] = wrow[k];
    }
    const float wih0 = W_ih[2 * j];
    const float wih1 = W_ih[2 * j + 1];
    const float bias = b_ih[j] + b_hh[j];

    // h0 = 0 for all NB batches of this group
    #pragma unroll
    for (int b = 0; b < NB; b++) hbuf[0][bl0 + b][j] = 0.0f;
    barrier_group(g);

    // x streams: one float4 = two timesteps, per batch
    const float4* xq[NB];
    float4 cur[NB];
    #pragma unroll
    for (int b = 0; b < NB; b++) {
        xq[b]  = reinterpret_cast<const float4*>(x + (size_t)(b0 + b) * TVAL * 2);
        cur[b] = xq[b][0];
    }

    // one RNN step for all NB batches: read hbuf[RB], write hbuf[WB]
    // XA[b]/XB[b] are the two input features for batch b at this timestep.
    #define RNN_STEP(RB, WB, XA, XB)                                             \
    {                                                                            \
        unsigned long long a0[NB], a1[NB];                                       \
        _Pragma("unroll")                                                        \
        for (int b = 0; b < NB; b++) {                                           \
            float base = fmaf((XA)[b], wih0, fmaf((XB)[b], wih1, bias));         \
            a0[b] = pack2(base, 0.0f);                                           \
            a1[b] = 0ull;                                                        \
        }                                                                        \
        const ulonglong2* hp[NB];                                                \
        _Pragma("unroll")                                                        \
        for (int b = 0; b < NB; b++)                                             \
            hp[b] = reinterpret_cast<const ulonglong2*>(&hbuf[(RB)][bl0 + b][0]);\
        _Pragma("unroll")                                                        \
        for (int kk = 0; kk < HVAL / 4; kk++) {                                  \
            ulonglong2 hv[NB];                                                   \
            _Pragma("unroll")                                                    \
            for (int b = 0; b < NB; b++) hv[b] = hp[b][kk];  /* LDS.128 bcast */ \
            _Pragma("unroll")                                                    \
            for (int b = 0; b < NB; b++) {                                       \
                a0[b] = ffma2(hv[b].x, w2[2 * kk],     a0[b]);                   \
                a1[b] = ffma2(hv[b].y, w2[2 * kk + 1], a1[b]);                   \
            }                                                                    \
        }                                                                        \
        _Pragma("unroll")                                                        \
        for (int b = 0; b < NB; b++) {                                           \
            unsigned long long sp = fadd2(a0[b], a1[b]);                         \
            float s = lo32(sp) + hi32(sp);                                       \
            hbuf[(WB)][bl0 + b][j] = fast_tanh(s);                               \
        }                                                                        \
        barrier_group(g);                                                        \
    }

    float xa[NB], xb[NB];
    #pragma unroll 1
    for (int t = 0; t < TVAL; t += 2) {
        // prefetch next pair of timesteps (clamped on the last iteration)
        int tn = (t + 2 < TVAL) ? (t / 2 + 1) : (TVAL / 2 - 1);
        float4 nxt[NB];
        #pragma unroll
        for (int b = 0; b < NB; b++) nxt[b] = xq[b][tn];

        #pragma unroll
        for (int b = 0; b < NB; b++) { xa[b] = cur[b].x; xb[b] = cur[b].y; }
        RNN_STEP(0, 1, xa, xb)
        #pragma unroll
        for (int b = 0; b < NB; b++) { xa[b] = cur[b].z; xb[b] = cur[b].w; }
        RNN_STEP(1, 0, xa, xb)

        #pragma unroll
        for (int b = 0; b < NB; b++) cur[b] = nxt[b];
    }
    #undef RNN_STEP

    // Final FC on h_T (in hbuf[0] after an even number of steps).
    // O=2, NB batches: threads j < 2*NB cover (batch, output) combos.
    if (j < 2 * NB) {
        const int which = j >> 1;          // batch within group
        const int oj    = j & 1;           // output index 0/1
        const float* hv  = &hbuf[0][bl0 + which][0];
        const float* wfc = W_fc + oj * HVAL;
        float acc = b_fc[oj];
        #pragma unroll
        for (int k = 0; k < HVAL; k++)
            acc = fmaf(hv[k], wfc[k], acc);
        out[(b0 + which) * 2 + oj] = acc;
    }
}

extern "C" void kernel_launch(void* const* d_in, const int* in_sizes, int n_in,
                              void* d_out, int out_size) {
    const float* x    = (const float*)d_in[0];
    const float* W_ih = (const float*)d_in[1];
    const float* W_hh = (const float*)d_in[2];
    const float* b_ih = (const float*)d_in[3];
    const float* b_hh = (const float*)d_in[4];
    const float* W_fc = (const float*)d_in[5];
    const float* b_fc = (const float*)d_in[6];
    rnn_kernel<<<GRID, THREADS>>>(x, W_ih, W_hh, b_ih, b_hh,
                                  W_fc, b_fc, (float*)d_out);
}

// round 6
// speedup vs baseline: 1.2206x; 1.2206x over previous
#include <cuda_runtime.h>
#include <cstdint>

// Problem constants (fixed by the dataset)
#define BVAL   2048
#define TVAL   2048
#define HVAL   64
#define NBW    2                    // batches per warp
#define WARPS  4                    // warps per CTA
#define BTILE  (NBW * WARPS)        // 8 batches per CTA
#define THREADS (WARPS * 32)        // 128 threads
#define GRID   (BVAL / BTILE)       // 256 CTAs, 2/SM resident -> single wave

// ---------- packed f32x2 helpers (Blackwell) ----------
__device__ __forceinline__ unsigned long long ffma2(unsigned long long a,
                                                    unsigned long long b,
                                                    unsigned long long c) {
    unsigned long long d;
    asm("fma.rn.f32x2 %0, %1, %2, %3;" : "=l"(d) : "l"(a), "l"(b), "l"(c));
    return d;
}
__device__ __forceinline__ unsigned long long fadd2(unsigned long long a,
                                                    unsigned long long b) {
    unsigned long long d;
    asm("add.rn.f32x2 %0, %1, %2;" : "=l"(d) : "l"(a), "l"(b));
    return d;
}
__device__ __forceinline__ float lo32(unsigned long long v) {
    return __uint_as_float((unsigned)v);
}
__device__ __forceinline__ float hi32(unsigned long long v) {
    return __uint_as_float((unsigned)(v >> 32));
}
__device__ __forceinline__ unsigned long long pack2(float lo, float hi) {
    return (unsigned long long)__float_as_uint(lo) |
           ((unsigned long long)__float_as_uint(hi) << 32);
}

// tanh via ex2/rcp approx: rel err ~1e-7 per step (safe over 2048 recurrent steps).
__device__ __forceinline__ float fast_tanh(float s) {
    float z = fminf(s * 2.885390082f, 126.0f);   // 2*log2(e)*s, clamped
    float p; asm("ex2.approx.f32 %0, %1;" : "=f"(p) : "f"(z));
    float num = p - 1.0f;
    float den = p + 1.0f;
    float r; asm("rcp.approx.f32 %0, %1;" : "=f"(r) : "f"(den));
    return num * r;   // z << 0 -> p = 0 -> exactly -1
}

__global__ void __launch_bounds__(THREADS)
rnn_kernel(const float* __restrict__ x,     // [B,T,2]
           const float* __restrict__ W_ih,  // [64,2]
           const float* __restrict__ W_hh,  // [64,64]
           const float* __restrict__ b_ih,  // [64]
           const float* __restrict__ b_hh,  // [64]
           const float* __restrict__ W_fc,  // [2,64]
           const float* __restrict__ b_fc,  // [2]
           float* __restrict__ out)         // [B,2]
{
    // double-buffered hidden state, batch-major. Each warp owns 2 batches;
    // no cross-warp synchronization needed after this point.
    __shared__ __align__(16) float hbuf[2][BTILE][HVAL];

    const int tid  = threadIdx.x;
    const int lane = tid & 31;
    const int w    = tid >> 5;          // warp 0..3
    const int j0   = lane;              // first output row this thread owns
    const int j1   = lane + 32;         // second output row
    const int bl0  = NBW * w;           // first local batch of this warp
    const int b0   = blockIdx.x * BTILE + bl0;

    // W_hh rows j0 and j1, k-packed into 32 u64 registers each (128 regs total,
    // shared across both batches)
    unsigned long long wA[HVAL / 2], wB[HVAL / 2];
    {
        const unsigned long long* ra =
            reinterpret_cast<const unsigned long long*>(W_hh + j0 * HVAL);
        const unsigned long long* rb =
            reinterpret_cast<const unsigned long long*>(W_hh + j1 * HVAL);
        #pragma unroll
        for (int k = 0; k < HVAL / 2; k++) { wA[k] = ra[k]; wB[k] = rb[k]; }
    }
    const float wihA0 = W_ih[2 * j0], wihA1 = W_ih[2 * j0 + 1];
    const float wihB0 = W_ih[2 * j1], wihB1 = W_ih[2 * j1 + 1];
    const float biasA = b_ih[j0] + b_hh[j0];
    const float biasB = b_ih[j1] + b_hh[j1];

    // h0 = 0 for both batches (each lane initializes its own 2 rows)
    hbuf[0][bl0 + 0][j0] = 0.0f;  hbuf[0][bl0 + 0][j1] = 0.0f;
    hbuf[0][bl0 + 1][j0] = 0.0f;  hbuf[0][bl0 + 1][j1] = 0.0f;
    __syncwarp();

    // x streams: one float4 = two timesteps, per batch (warp-uniform address)
    const float4* xq0 = reinterpret_cast<const float4*>(x + (size_t)(b0 + 0) * TVAL * 2);
    const float4* xq1 = reinterpret_cast<const float4*>(x + (size_t)(b0 + 1) * TVAL * 2);
    float4 c0 = xq0[0];
    float4 c1 = xq1[0];

    // one RNN step for both batches: read hbuf[RB], write hbuf[WB]
    // (XA0,XB0) = features for batch 0, (XA1,XB1) for batch 1.
    #define RNN_STEP(RB, WB, XA0, XB0, XA1, XB1)                                 \
    {                                                                            \
        float baseA0 = fmaf((XA0), wihA0, fmaf((XB0), wihA1, biasA));            \
        float baseB0 = fmaf((XA0), wihB0, fmaf((XB0), wihB1, biasB));            \
        float baseA1 = fmaf((XA1), wihA0, fmaf((XB1), wihA1, biasA));            \
        float baseB1 = fmaf((XA1), wihB0, fmaf((XB1), wihB1, biasB));            \
        unsigned long long aA0 = pack2(baseA0, 0.0f), aA0b = 0ull;               \
        unsigned long long aB0 = pack2(baseB0, 0.0f), aB0b = 0ull;               \
        unsigned long long aA1 = pack2(baseA1, 0.0f), aA1b = 0ull;               \
        unsigned long long aB1 = pack2(baseB1, 0.0f), aB1b = 0ull;               \
        const ulonglong2* hp0 =                                                  \
            reinterpret_cast<const ulonglong2*>(&hbuf[(RB)][bl0 + 0][0]);        \
        const ulonglong2* hp1 =                                                  \
            reinterpret_cast<const ulonglong2*>(&hbuf[(RB)][bl0 + 1][0]);        \
        _Pragma("unroll")                                                        \
        for (int kk = 0; kk < HVAL / 4; kk++) {                                  \
            ulonglong2 hv0 = hp0[kk];          /* LDS.128, broadcast */          \
            ulonglong2 hv1 = hp1[kk];                                            \
            aA0  = ffma2(hv0.x, wA[2 * kk],     aA0);                            \
            aA0b = ffma2(hv0.y, wA[2 * kk + 1], aA0b);                           \
            aB0  = ffma2(hv0.x, wB[2 * kk],     aB0);                            \
            aB0b = ffma2(hv0.y, wB[2 * kk + 1], aB0b);                           \
            aA1  = ffma2(hv1.x, wA[2 * kk],     aA1);                            \
            aA1b = ffma2(hv1.y, wA[2 * kk + 1], aA1b);                           \
            aB1  = ffma2(hv1.x, wB[2 * kk],     aB1);                            \
            aB1b = ffma2(hv1.y, wB[2 * kk + 1], aB1b);                           \
        }                                                                        \
        unsigned long long sA0 = fadd2(aA0, aA0b);                               \
        unsigned long long sB0 = fadd2(aB0, aB0b);                               \
        unsigned long long sA1 = fadd2(aA1, aA1b);                               \
        unsigned long long sB1 = fadd2(aB1, aB1b);                               \
        hbuf[(WB)][bl0 + 0][j0] = fast_tanh(lo32(sA0) + hi32(sA0));              \
        hbuf[(WB)][bl0 + 0][j1] = fast_tanh(lo32(sB0) + hi32(sB0));              \
        hbuf[(WB)][bl0 + 1][j0] = fast_tanh(lo32(sA1) + hi32(sA1));              \
        hbuf[(WB)][bl0 + 1][j1] = fast_tanh(lo32(sB1) + hi32(sB1));              \
        __syncwarp();                                                            \
    }

    #pragma unroll 1
    for (int t = 0; t < TVAL; t += 2) {
        // prefetch next pair of timesteps (clamped on the last iteration)
        int tn = (t + 2 < TVAL) ? (t / 2 + 1) : (TVAL / 2 - 1);
        float4 n0 = xq0[tn];
        float4 n1 = xq1[tn];
        RNN_STEP(0, 1, c0.x, c0.y, c1.x, c1.y)
        RNN_STEP(1, 0, c0.z, c0.w, c1.z, c1.w)
        c0 = n0;
        c1 = n1;
    }
    #undef RNN_STEP

    // Final FC on h_T (in hbuf[0] after an even number of steps).
    // O=2, 2 batches per warp: lanes 0..3 cover (batch, output) combos.
    if (lane < 4) {
        const int which = lane >> 1;       // batch within warp pair
        const int oj    = lane & 1;        // output index 0/1
        const float* hv  = &hbuf[0][bl0 + which][0];
        const float* wfc = W_fc + oj * HVAL;
        float acc = b_fc[oj];
        #pragma unroll
        for (int k = 0; k < HVAL; k++)
            acc = fmaf(hv[k], wfc[k], acc);
        out[(b0 + which) * 2 + oj] = acc;
    }
}

extern "C" void kernel_launch(void* const* d_in, const int* in_sizes, int n_in,
                              void* d_out, int out_size) {
    const float* x    = (const float*)d_in[0];
    const float* W_ih = (const float*)d_in[1];
    const float* W_hh = (const float*)d_in[2];
    const float* b_ih = (const float*)d_in[3];
    const float* b_hh = (const float*)d_in[4];
    const float* W_fc = (const float*)d_in[5];
    const float* b_fc = (const float*)d_in[6];
    rnn_kernel<<<GRID, THREADS>>>(x, W_ih, W_hh, b_ih, b_hh,
                                  W_fc, b_fc, (float*)d_out);
}